// round 1
// baseline (speedup 1.0000x reference)
#include <cuda_runtime.h>
#include <math.h>

// Problem shapes (fixed by the bench)
#define B_SZ 1024
#define N_SZ 100000
#define D_SZ 512
#define D4   (D_SZ/4)          // 128 float4 per row
#define BM   16                // query rows per CTA (8 warps x 2 rows)
#define BN   64                // keys per step
#define NSPLIT 7
#define SPL  ((N_SZ + NSPLIT - 1)/NSPLIT)   // 14286
#define THREADS 256

#define SMEM_BYTES (BM*D4*16 + D4*BN*16 + BN*4 + BM*BN*4)  // 168192

// Scratch (static device globals; allocation inside kernel_launch is forbidden)
__device__ float g_dsn[N_SZ];
__device__ float g_ml[B_SZ * NSPLIT * 2];
__device__ float g_acc[(size_t)B_SZ * NSPLIT * D_SZ];

__device__ __forceinline__ float dot4(float4 a, float4 b) {
    return fmaf(a.x, b.x, fmaf(a.y, b.y, fmaf(a.z, b.z, a.w * b.w)));
}
__device__ __forceinline__ void fma4(float4& a, float p, float4 v) {
    a.x = fmaf(p, v.x, a.x); a.y = fmaf(p, v.y, a.y);
    a.z = fmaf(p, v.z, a.z); a.w = fmaf(p, v.w, a.w);
}

// ---------------------------------------------------------------------------
// Kernel 1: dataset row norms  dsn[n] = sum_d y[n][d]^2   (one warp per row)
// ---------------------------------------------------------------------------
__global__ void dsn_kernel(const float* __restrict__ y) {
    int warp = threadIdx.x >> 5, lane = threadIdx.x & 31;
    int n = blockIdx.x * 8 + warp;
    if (n >= N_SZ) return;
    const float4* y4 = (const float4*)y;
    float s = 0.f;
    #pragma unroll
    for (int k = 0; k < 4; k++) {
        float4 v = y4[(size_t)n * D4 + lane + 32 * k];
        s += dot4(v, v);
    }
    #pragma unroll
    for (int off = 16; off > 0; off >>= 1)
        s += __shfl_xor_sync(0xffffffffu, s, off);
    if (lane == 0) g_dsn[n] = s;
}

// ---------------------------------------------------------------------------
// Kernel 2: fused flash pass.
// logit'[b][n] = (a/b^2) * <x_b, y_n>  -  (a^2/(2 b^2)) * dsn[n]
// (the ||x_b||^2 row constant cancels in softmax)
// Online softmax over the split's key range; per-(row,split) partials
// (m, l, acc[512]) go to global scratch.
//
// smem key tile is XOR-swizzled: float4 (n, j) stored at sy[j*BN + (n ^ (j&63))]
//  -> QK reads (lane = n, j varying)    : conflict-free
//  -> PV reads (lane -> j, n varying)   : conflict-free
// ---------------------------------------------------------------------------
__global__ __launch_bounds__(THREADS) void flash_kernel(
    const float* __restrict__ x, const float* __restrict__ t,
    const float* __restrict__ y)
{
    extern __shared__ char smem_raw[];
    float4* sx   = (float4*)smem_raw;            // BM * D4
    float4* sy   = sx + BM * D4;                 // D4 * BN (swizzled)
    float*  sdsn = (float*)(sy + D4 * BN);       // BN
    float*  sp   = sdsn + BN;                    // BM * BN

    const int tid  = threadIdx.x;
    const int lane = tid & 31;
    const int warp = tid >> 5;
    const int r0      = blockIdx.x * BM;
    const int n_begin = blockIdx.y * SPL;
    const int n_end   = min(n_begin + SPL, N_SZ);

    // Load query tile (contiguous rows)
    const float4* x4 = (const float4*)x;
    for (int i = tid; i < BM * D4; i += THREADS)
        sx[i] = x4[(size_t)r0 * D4 + i];

    // Per-warp rows rA = r0+2*warp, rB = rA+1
    const float ta = t[r0 + 2 * warp];
    const float tb = t[r0 + 2 * warp + 1];
    const float aA = ta, bA = 1.f - ta;
    const float aB = tb, bB = 1.f - tb;
    const float alA = aA / (bA * bA), beA = aA * aA / (2.f * bA * bA);
    const float alB = aB / (bB * bB), beB = aB * aB / (2.f * bB * bB);

    float mrunA = -INFINITY, mrunB = -INFINITY;
    float lrunA = 0.f, lrunB = 0.f;
    float4 accA[4], accB[4];   // lane holds d4 = lane + 32*k
    #pragma unroll
    for (int k = 0; k < 4; k++) {
        accA[k] = make_float4(0.f, 0.f, 0.f, 0.f);
        accB[k] = make_float4(0.f, 0.f, 0.f, 0.f);
    }

    const float4* y4g = (const float4*)y;
    const int nl0 = lane, nl1 = lane + 32;

    for (int n0 = n_begin; n0 < n_end; n0 += BN) {
        __syncthreads();   // previous iteration's readers done with sy/sp
        // Load key tile (zero-fill tail), swizzled store
        for (int i = tid; i < BN * D4; i += THREADS) {
            int n = i >> 7;          // i / D4
            int j = i & (D4 - 1);    // i % D4
            float4 v = make_float4(0.f, 0.f, 0.f, 0.f);
            if (n0 + n < n_end) v = y4g[(size_t)(n0 + n) * D4 + j];
            sy[j * BN + (n ^ (j & 63))] = v;
        }
        if (tid < BN) sdsn[tid] = (n0 + tid < n_end) ? g_dsn[n0 + tid] : 0.f;
        __syncthreads();

        // ---- QK: each lane computes 2 rows x 2 keys, 2 accumulator chains ----
        float sA0a = 0.f, sA0b = 0.f, sA1a = 0.f, sA1b = 0.f;
        float sB0a = 0.f, sB0b = 0.f, sB1a = 0.f, sB1b = 0.f;
        #pragma unroll 8
        for (int j = 0; j < D4; j++) {
            float4 xa = sx[(2 * warp) * D4 + j];
            float4 xb = sx[(2 * warp + 1) * D4 + j];
            int c = j & 63;
            float4 y0 = sy[j * BN + (nl0 ^ c)];
            float4 y1 = sy[j * BN + (nl1 ^ c)];
            if (j & 1) {
                sA0b += dot4(xa, y0); sA1b += dot4(xa, y1);
                sB0b += dot4(xb, y0); sB1b += dot4(xb, y1);
            } else {
                sA0a += dot4(xa, y0); sA1a += dot4(xa, y1);
                sB0a += dot4(xb, y0); sB1a += dot4(xb, y1);
            }
        }
        float sA0 = sA0a + sA0b, sA1 = sA1a + sA1b;
        float sB0 = sB0a + sB0b, sB1 = sB1a + sB1b;

        bool v0 = (n0 + nl0) < n_end;
        bool v1 = (n0 + nl1) < n_end;
        float d0 = sdsn[nl0], d1 = sdsn[nl1];
        float lgA0 = v0 ? fmaf(alA, sA0, -beA * d0) : -INFINITY;
        float lgA1 = v1 ? fmaf(alA, sA1, -beA * d1) : -INFINITY;
        float lgB0 = v0 ? fmaf(alB, sB0, -beB * d0) : -INFINITY;
        float lgB1 = v1 ? fmaf(alB, sB1, -beB * d1) : -INFINITY;

        // ---- online softmax update (both rows in parallel) ----
        float mtA = fmaxf(lgA0, lgA1);
        float mtB = fmaxf(lgB0, lgB1);
        #pragma unroll
        for (int off = 16; off > 0; off >>= 1) {
            mtA = fmaxf(mtA, __shfl_xor_sync(0xffffffffu, mtA, off));
            mtB = fmaxf(mtB, __shfl_xor_sync(0xffffffffu, mtB, off));
        }
        float mnewA = fmaxf(mrunA, mtA);
        float mnewB = fmaxf(mrunB, mtB);
        float scA = (mrunA == -INFINITY) ? 0.f : __expf(mrunA - mnewA);
        float scB = (mrunB == -INFINITY) ? 0.f : __expf(mrunB - mnewB);
        float pA0 = __expf(lgA0 - mnewA), pA1 = __expf(lgA1 - mnewA);
        float pB0 = __expf(lgB0 - mnewB), pB1 = __expf(lgB1 - mnewB);
        float psA = pA0 + pA1, psB = pB0 + pB1;
        #pragma unroll
        for (int off = 16; off > 0; off >>= 1) {
            psA += __shfl_xor_sync(0xffffffffu, psA, off);
            psB += __shfl_xor_sync(0xffffffffu, psB, off);
        }
        lrunA = lrunA * scA + psA;
        lrunB = lrunB * scB + psB;
        mrunA = mnewA; mrunB = mnewB;
        #pragma unroll
        for (int k = 0; k < 4; k++) {
            accA[k].x *= scA; accA[k].y *= scA; accA[k].z *= scA; accA[k].w *= scA;
            accB[k].x *= scB; accB[k].y *= scB; accB[k].z *= scB; accB[k].w *= scB;
        }

        // share p across the warp (each warp touches only its own 2 rows)
        sp[(2 * warp) * BN + nl0] = pA0;
        sp[(2 * warp) * BN + nl1] = pA1;
        sp[(2 * warp + 1) * BN + nl0] = pB0;
        sp[(2 * warp + 1) * BN + nl1] = pB1;
        __syncwarp();

        // ---- PV: acc[d4 = lane+32k] += p[n] * y[n][d4] ----
        #pragma unroll 4
        for (int n = 0; n < BN; n++) {
            float pa = sp[(2 * warp) * BN + n];
            float pb = sp[(2 * warp + 1) * BN + n];
            #pragma unroll
            for (int k = 0; k < 4; k++) {
                int j = lane + 32 * k;
                float4 yv = sy[j * BN + (n ^ (j & 63))];
                fma4(accA[k], pa, yv);
                fma4(accB[k], pb, yv);
            }
        }
    }

    // ---- write per-(row,split) partials ----
    float4* gacc4 = (float4*)g_acc;
    {
        int rA = r0 + 2 * warp;
        int rB = rA + 1;
        size_t baseA = ((size_t)rA * NSPLIT + blockIdx.y) * D4;
        size_t baseB = ((size_t)rB * NSPLIT + blockIdx.y) * D4;
        #pragma unroll
        for (int k = 0; k < 4; k++) {
            gacc4[baseA + lane + 32 * k] = accA[k];
            gacc4[baseB + lane + 32 * k] = accB[k];
        }
        if (lane == 0) {
            g_ml[(rA * NSPLIT + blockIdx.y) * 2 + 0] = mrunA;
            g_ml[(rA * NSPLIT + blockIdx.y) * 2 + 1] = lrunA;
            g_ml[(rB * NSPLIT + blockIdx.y) * 2 + 0] = mrunB;
            g_ml[(rB * NSPLIT + blockIdx.y) * 2 + 1] = lrunB;
        }
    }
}

// ---------------------------------------------------------------------------
// Kernel 3: combine splits + final affine
// v = (-1/b) * x  +  (1 + a/b) * softmax_weighted_dataset
// ---------------------------------------------------------------------------
__global__ void combine_kernel(const float* __restrict__ x,
                               const float* __restrict__ t,
                               float* __restrict__ out)
{
    int r = blockIdx.x;
    int tid = threadIdx.x;   // 128 threads, one float4 of D each

    float ms[NSPLIT], ls[NSPLIT];
    float M = -INFINITY;
    #pragma unroll
    for (int s = 0; s < NSPLIT; s++) {
        ms[s] = g_ml[(r * NSPLIT + s) * 2 + 0];
        ls[s] = g_ml[(r * NSPLIT + s) * 2 + 1];
        M = fmaxf(M, ms[s]);
    }
    float w[NSPLIT];
    float L = 0.f;
    #pragma unroll
    for (int s = 0; s < NSPLIT; s++) {
        w[s] = __expf(ms[s] - M);
        L = fmaf(w[s], ls[s], L);
    }
    float a = t[r], b = 1.f - a;
    float c1 = -1.f / b;
    float c2 = (1.f + a / b) / L;

    const float4* gacc4 = (const float4*)g_acc;
    float4 ws = make_float4(0.f, 0.f, 0.f, 0.f);
    #pragma unroll
    for (int s = 0; s < NSPLIT; s++) {
        float4 v = gacc4[((size_t)r * NSPLIT + s) * D4 + tid];
        fma4(ws, w[s], v);
    }
    float4 xv = ((const float4*)x)[(size_t)r * D4 + tid];
    float4 o;
    o.x = fmaf(c1, xv.x, c2 * ws.x);
    o.y = fmaf(c1, xv.y, c2 * ws.y);
    o.z = fmaf(c1, xv.z, c2 * ws.z);
    o.w = fmaf(c1, xv.w, c2 * ws.w);
    ((float4*)out)[(size_t)r * D4 + tid] = o;
}

// ---------------------------------------------------------------------------
extern "C" void kernel_launch(void* const* d_in, const int* in_sizes, int n_in,
                              void* d_out, int out_size)
{
    const float* x = (const float*)d_in[0];   // x_t   (1024, 512)
    const float* t = (const float*)d_in[1];   // t     (1024,)
    const float* y = (const float*)d_in[2];   // dataset (100000, 512)
    float* out = (float*)d_out;

    cudaFuncSetAttribute(flash_kernel,
                         cudaFuncAttributeMaxDynamicSharedMemorySize, SMEM_BYTES);

    dsn_kernel<<<N_SZ / 8, 256>>>(y);
    flash_kernel<<<dim3(B_SZ / BM, NSPLIT), THREADS, SMEM_BYTES>>>(x, t, y);
    combine_kernel<<<B_SZ, D4>>>(x, t, out);
}

// round 2
// speedup vs baseline: 1.9609x; 1.9609x over previous
#include <cuda_runtime.h>
#include <math.h>

// Problem shapes (fixed)
#define B_SZ 1024
#define N_SZ 100000
#define D_SZ 512
#define D4   128               // float4 per row
#define BM   32                // rows per CTA (8 warps x 4 rows)
#define BN   64                // keys per tile (2 keys per lane)
#define NSPLIT 9
#define SPL  11112             // ceil(N/NSPLIT)
#define THREADS 256
#define NROWBLK (B_SZ/BM)      // 32

#define SMEM_BYTES (BM*D4*16 + D4*BN*16 + BM*BN*8)   // 65536+131072+16384 = 212992

// Scratch
__device__ float g_ml[B_SZ * NSPLIT * 2];
__device__ float g_acc[(size_t)B_SZ * NSPLIT * D_SZ];
__device__ int   g_cnt[NROWBLK];   // zero-initialized; last CTA resets after use

// ---- packed f32x2 helpers (SASS FFMA2 — only reachable via PTX) ----
typedef unsigned long long u64;
__device__ __forceinline__ u64 pack2(float a, float b) {
    u64 r; asm("mov.b64 %0,{%1,%2};" : "=l"(r) : "f"(a), "f"(b)); return r;
}
__device__ __forceinline__ void unpack2(u64 v, float& a, float& b) {
    asm("mov.b64 {%0,%1},%2;" : "=f"(a), "=f"(b) : "l"(v));
}
__device__ __forceinline__ void ffma2(u64& d, u64 a, u64 b) {
    asm("fma.rn.f32x2 %0,%1,%2,%0;" : "+l"(d) : "l"(a), "l"(b));
}
__device__ __forceinline__ void fmul2(u64& d, u64 a) {
    asm("mul.rn.f32x2 %0,%0,%1;" : "+l"(d) : "l"(a));
}

// ---------------------------------------------------------------------------
// One fused kernel: flash pass (QK + online softmax + PV) with on-the-fly
// dataset norms, split-K over keys, and last-CTA-per-row-block combine epilogue.
// logit'[b][n] = (a/b^2) * <x_b,y_n> - (a^2/(2b^2)) * ||y_n||^2   (||x||^2 cancels)
// v = (-1/b) x + (1 + a/b) * softmax-weighted dataset
// ---------------------------------------------------------------------------
__global__ __launch_bounds__(THREADS, 1) void flash_kernel(
    const float* __restrict__ x, const float* __restrict__ t,
    const float* __restrict__ y, float* __restrict__ out)
{
    extern __shared__ char smem_raw[];
    ulonglong2* sx = (ulonglong2*)smem_raw;          // BM*D4 (float4 each)
    ulonglong2* sy = sx + BM * D4;                   // D4*BN, swizzled
    u64*        sp = (u64*)(sy + (size_t)D4 * BN);   // BM*BN packed {p,p}
    __shared__ int s_last;

    const int tid  = threadIdx.x;
    const int lane = tid & 31;
    const int warp = tid >> 5;
    const int rb      = blockIdx.x;
    const int r0      = rb * BM;
    const int split   = blockIdx.y;
    const int n_begin = split * SPL;
    const int n_end   = min(n_begin + SPL, N_SZ);

    // query tile -> smem
    const float4* x4 = (const float4*)x;
    for (int i = tid; i < BM * D4; i += THREADS)
        ((float4*)sx)[i] = x4[(size_t)r0 * D4 + i];

    // per-row coefficients (4 rows per warp)
    float al[4], be[4];
    #pragma unroll
    for (int r = 0; r < 4; r++) {
        float tv = t[r0 + warp * 4 + r];
        float a = tv, b = 1.f - tv;
        al[r] = a / (b * b);
        be[r] = a * a / (2.f * b * b);
    }

    float mrun[4] = {-INFINITY, -INFINITY, -INFINITY, -INFINITY};
    float lrun[4] = {0.f, 0.f, 0.f, 0.f};
    u64 acc[4][8];                       // lane owns d4 = lane+32k -> 2 u64 per k
    #pragma unroll
    for (int r = 0; r < 4; r++)
        #pragma unroll
        for (int i = 0; i < 8; i++) acc[r][i] = 0ull;

    const float4* y4g = (const float4*)y;
    const int nl0 = lane, nl1 = lane + 32;

    for (int n0 = n_begin; n0 < n_end; n0 += BN) {
        __syncthreads();
        // key tile -> smem (swizzled: float4 (n,j) at sy[j*BN + (n ^ (j&63))])
        for (int i = tid; i < BN * D4; i += THREADS) {
            int n = i >> 7, j = i & 127;
            float4 v = make_float4(0.f, 0.f, 0.f, 0.f);
            if (n0 + n < n_end) v = y4g[(size_t)(n0 + n) * D4 + j];
            ((float4*)sy)[j * BN + (n ^ (j & 63))] = v;
        }
        __syncthreads();

        // ---- QK (+ on-the-fly key norms) ----
        u64 s[4][2];
        #pragma unroll
        for (int r = 0; r < 4; r++) { s[r][0] = 0ull; s[r][1] = 0ull; }
        u64 ny0 = 0ull, ny1 = 0ull;

        #pragma unroll 4
        for (int j = 0; j < D4; j++) {
            int c = j & 63;
            ulonglong2 yv0 = sy[j * BN + (nl0 ^ c)];
            ulonglong2 yv1 = sy[j * BN + (nl1 ^ c)];
            ffma2(ny0, yv0.x, yv0.x); ffma2(ny0, yv0.y, yv0.y);
            ffma2(ny1, yv1.x, yv1.x); ffma2(ny1, yv1.y, yv1.y);
            #pragma unroll
            for (int r = 0; r < 4; r++) {
                ulonglong2 xv = sx[(warp * 4 + r) * D4 + j];   // broadcast
                ffma2(s[r][0], xv.x, yv0.x); ffma2(s[r][0], xv.y, yv0.y);
                ffma2(s[r][1], xv.x, yv1.x); ffma2(s[r][1], xv.y, yv1.y);
            }
        }

        bool v0 = (n0 + nl0) < n_end;
        bool v1 = (n0 + nl1) < n_end;
        float t0, t1;
        unpack2(ny0, t0, t1); float dn0 = t0 + t1;
        unpack2(ny1, t0, t1); float dn1 = t0 + t1;

        float lg0[4], lg1[4];
        #pragma unroll
        for (int r = 0; r < 4; r++) {
            float slo, shi, sv;
            unpack2(s[r][0], slo, shi); sv = slo + shi;
            lg0[r] = v0 ? fmaf(al[r], sv, -be[r] * dn0) : -INFINITY;
            unpack2(s[r][1], slo, shi); sv = slo + shi;
            lg1[r] = v1 ? fmaf(al[r], sv, -be[r] * dn1) : -INFINITY;
        }

        // ---- online softmax (4 rows) ----
        #pragma unroll
        for (int r = 0; r < 4; r++) {
            float mt = fmaxf(lg0[r], lg1[r]);
            #pragma unroll
            for (int off = 16; off > 0; off >>= 1)
                mt = fmaxf(mt, __shfl_xor_sync(0xffffffffu, mt, off));
            float mnew = fmaxf(mrun[r], mt);
            float sc = (mrun[r] == -INFINITY) ? 0.f : __expf(mrun[r] - mnew);
            float p0 = __expf(lg0[r] - mnew);
            float p1 = __expf(lg1[r] - mnew);
            float ps = p0 + p1;
            #pragma unroll
            for (int off = 16; off > 0; off >>= 1)
                ps += __shfl_xor_sync(0xffffffffu, ps, off);
            lrun[r] = lrun[r] * sc + ps;
            mrun[r] = mnew;
            u64 scp = pack2(sc, sc);
            #pragma unroll
            for (int i = 0; i < 8; i++) fmul2(acc[r][i], scp);
            sp[(warp * 4 + r) * BN + nl0] = pack2(p0, p0);
            sp[(warp * 4 + r) * BN + nl1] = pack2(p1, p1);
        }
        __syncwarp();

        // ---- PV ----
        #pragma unroll 2
        for (int n = 0; n < BN; n++) {
            u64 p0 = sp[(warp * 4 + 0) * BN + n];
            u64 p1 = sp[(warp * 4 + 1) * BN + n];
            u64 p2 = sp[(warp * 4 + 2) * BN + n];
            u64 p3 = sp[(warp * 4 + 3) * BN + n];
            #pragma unroll
            for (int k = 0; k < 4; k++) {
                int j = lane + 32 * k;
                ulonglong2 yv = sy[j * BN + (n ^ (j & 63))];
                ffma2(acc[0][2*k], p0, yv.x); ffma2(acc[0][2*k+1], p0, yv.y);
                ffma2(acc[1][2*k], p1, yv.x); ffma2(acc[1][2*k+1], p1, yv.y);
                ffma2(acc[2][2*k], p2, yv.x); ffma2(acc[2][2*k+1], p2, yv.y);
                ffma2(acc[3][2*k], p3, yv.x); ffma2(acc[3][2*k+1], p3, yv.y);
            }
        }
    }

    // ---- write per-(row,split) partials ----
    {
        ulonglong2* gacc2 = (ulonglong2*)g_acc;
        #pragma unroll
        for (int r = 0; r < 4; r++) {
            int row = r0 + warp * 4 + r;
            size_t base = ((size_t)row * NSPLIT + split) * D4;
            #pragma unroll
            for (int k = 0; k < 4; k++)
                gacc2[base + lane + 32 * k] =
                    make_ulonglong2(acc[r][2*k], acc[r][2*k+1]);
            if (lane == 0) {
                g_ml[(row * NSPLIT + split) * 2 + 0] = mrun[r];
                g_ml[(row * NSPLIT + split) * 2 + 1] = lrun[r];
            }
        }
    }

    // ---- last-CTA combine epilogue ----
    __threadfence();
    __syncthreads();
    if (tid == 0) {
        int old = atomicAdd(&g_cnt[rb], 1);
        s_last = (old == NSPLIT - 1) ? 1 : 0;
    }
    __syncthreads();
    if (!s_last) return;
    __threadfence();

    {
        int row = r0 + (tid >> 3);           // 8 threads per row
        int jc  = tid & 7;
        float ms[NSPLIT], ls[NSPLIT];
        float M = -INFINITY;
        #pragma unroll
        for (int s = 0; s < NSPLIT; s++) {
            float2 ml = __ldcg((const float2*)&g_ml[(row * NSPLIT + s) * 2]);
            ms[s] = ml.x; ls[s] = ml.y;
            M = fmaxf(M, ms[s]);
        }
        float w[NSPLIT], L = 0.f;
        #pragma unroll
        for (int s = 0; s < NSPLIT; s++) {
            w[s] = __expf(ms[s] - M);
            L = fmaf(w[s], ls[s], L);
        }
        float a = t[row], b = 1.f - a;
        float c1 = -1.f / b;
        float c2 = (1.f + a / b) / L;

        const float4* gacc4 = (const float4*)g_acc;
        #pragma unroll 4
        for (int q = 0; q < 16; q++) {
            int j = jc + 8 * q;
            float4 ws = make_float4(0.f, 0.f, 0.f, 0.f);
            #pragma unroll
            for (int s = 0; s < NSPLIT; s++) {
                float4 v = __ldcg(&gacc4[((size_t)row * NSPLIT + s) * D4 + j]);
                ws.x = fmaf(w[s], v.x, ws.x); ws.y = fmaf(w[s], v.y, ws.y);
                ws.z = fmaf(w[s], v.z, ws.z); ws.w = fmaf(w[s], v.w, ws.w);
            }
            float4 xv = x4[(size_t)row * D4 + j];
            float4 o;
            o.x = fmaf(c1, xv.x, c2 * ws.x);
            o.y = fmaf(c1, xv.y, c2 * ws.y);
            o.z = fmaf(c1, xv.z, c2 * ws.z);
            o.w = fmaf(c1, xv.w, c2 * ws.w);
            ((float4*)out)[(size_t)row * D4 + j] = o;
        }
    }
    __syncthreads();
    if (tid == 0) g_cnt[rb] = 0;   // reset for next graph replay
}

// ---------------------------------------------------------------------------
extern "C" void kernel_launch(void* const* d_in, const int* in_sizes, int n_in,
                              void* d_out, int out_size)
{
    const float* x = (const float*)d_in[0];   // x_t (1024,512)
    const float* t = (const float*)d_in[1];   // t (1024,)
    const float* y = (const float*)d_in[2];   // dataset (100000,512)
    float* out = (float*)d_out;

    cudaFuncSetAttribute(flash_kernel,
                         cudaFuncAttributeMaxDynamicSharedMemorySize, SMEM_BYTES);
    flash_kernel<<<dim3(NROWBLK, NSPLIT), THREADS, SMEM_BYTES>>>(x, t, y, out);
}

// round 3
// speedup vs baseline: 1.9756x; 1.0075x over previous
#include <cuda_runtime.h>
#include <math.h>

// Problem shapes (fixed)
#define B_SZ 1024
#define N_SZ 100000
#define D_SZ 512
#define D4   128               // float4 per row
#define BM   32                // rows per CTA (8 warps x 4 rows)
#define BN   64                // keys per tile (2 keys per lane)
#define NSPLIT 9
#define SPL  11112             // ceil(N/NSPLIT)
#define THREADS 256
#define NROWBLK (B_SZ/BM)      // 32

#define SMEM_BYTES (BM*D4*16 + D4*BN*16 + BM*BN*8)   // 65536+131072+16384 = 212992

// Scratch
__device__ float g_ml[B_SZ * NSPLIT * 2];
__device__ float g_acc[(size_t)B_SZ * NSPLIT * D_SZ];
__device__ int   g_cnt[NROWBLK];   // zero-initialized; last CTA resets after use

// ---- packed f32x2 helpers (SASS FFMA2 — only reachable via PTX) ----
typedef unsigned long long u64;
__device__ __forceinline__ u64 pack2(float a, float b) {
    u64 r; asm("mov.b64 %0,{%1,%2};" : "=l"(r) : "f"(a), "f"(b)); return r;
}
__device__ __forceinline__ void unpack2(u64 v, float& a, float& b) {
    asm("mov.b64 {%0,%1},%2;" : "=f"(a), "=f"(b) : "l"(v));
}
__device__ __forceinline__ void ffma2(u64& d, u64 a, u64 b) {
    asm("fma.rn.f32x2 %0,%1,%2,%0;" : "+l"(d) : "l"(a), "l"(b));
}
__device__ __forceinline__ void fmul2(u64& d, u64 a) {
    asm("mul.rn.f32x2 %0,%0,%1;" : "+l"(d) : "l"(a));
}

// ---------------------------------------------------------------------------
// One fused kernel: flash pass (QK + online softmax + PV) with on-the-fly
// dataset norms, split-K over keys, and last-CTA-per-row-block combine epilogue.
// logit'[b][n] = (a/b^2) * <x_b,y_n> - (a^2/(2b^2)) * ||y_n||^2   (||x||^2 cancels)
// v = (-1/b) x + (1 + a/b) * softmax-weighted dataset
// ---------------------------------------------------------------------------
__global__ __launch_bounds__(THREADS, 1) void flash_kernel(
    const float* __restrict__ x, const float* __restrict__ t,
    const float* __restrict__ y, float* __restrict__ out)
{
    extern __shared__ char smem_raw[];
    ulonglong2* sx = (ulonglong2*)smem_raw;          // BM*D4 (float4 each)
    ulonglong2* sy = sx + BM * D4;                   // D4*BN, swizzled
    u64*        sp = (u64*)(sy + (size_t)D4 * BN);   // BM*BN packed {p,p}
    __shared__ int s_last;

    const int tid  = threadIdx.x;
    const int lane = tid & 31;
    const int warp = tid >> 5;
    const int rb      = blockIdx.x;
    const int r0      = rb * BM;
    const int split   = blockIdx.y;
    const int n_begin = split * SPL;
    const int n_end   = min(n_begin + SPL, N_SZ);

    // query tile -> smem
    const float4* x4 = (const float4*)x;
    for (int i = tid; i < BM * D4; i += THREADS)
        ((float4*)sx)[i] = x4[(size_t)r0 * D4 + i];

    // per-row coefficients (4 rows per warp)
    float al[4], be[4];
    #pragma unroll
    for (int r = 0; r < 4; r++) {
        float tv = t[r0 + warp * 4 + r];
        float a = tv, b = 1.f - tv;
        al[r] = a / (b * b);
        be[r] = a * a / (2.f * b * b);
    }

    float mrun[4] = {-INFINITY, -INFINITY, -INFINITY, -INFINITY};
    float lrun[4] = {0.f, 0.f, 0.f, 0.f};
    u64 acc[4][8];                       // lane owns d4 = lane+32k -> 2 u64 per k
    #pragma unroll
    for (int r = 0; r < 4; r++)
        #pragma unroll
        for (int i = 0; i < 8; i++) acc[r][i] = 0ull;

    const float4* y4g = (const float4*)y;
    const int nl0 = lane, nl1 = lane + 32;

    for (int n0 = n_begin; n0 < n_end; n0 += BN) {
        __syncthreads();
        // key tile -> smem (swizzled: float4 (n,j) at sy[j*BN + (n ^ (j&63))])
        for (int i = tid; i < BN * D4; i += THREADS) {
            int n = i >> 7, j = i & 127;
            float4 v = make_float4(0.f, 0.f, 0.f, 0.f);
            if (n0 + n < n_end) v = y4g[(size_t)(n0 + n) * D4 + j];
            ((float4*)sy)[j * BN + (n ^ (j & 63))] = v;
        }
        __syncthreads();

        // ---- QK (+ on-the-fly key norms) ----
        u64 s[4][2];
        #pragma unroll
        for (int r = 0; r < 4; r++) { s[r][0] = 0ull; s[r][1] = 0ull; }
        u64 ny0 = 0ull, ny1 = 0ull;

        #pragma unroll 4
        for (int j = 0; j < D4; j++) {
            int c = j & 63;
            ulonglong2 yv0 = sy[j * BN + (nl0 ^ c)];
            ulonglong2 yv1 = sy[j * BN + (nl1 ^ c)];
            ffma2(ny0, yv0.x, yv0.x); ffma2(ny0, yv0.y, yv0.y);
            ffma2(ny1, yv1.x, yv1.x); ffma2(ny1, yv1.y, yv1.y);
            #pragma unroll
            for (int r = 0; r < 4; r++) {
                ulonglong2 xv = sx[(warp * 4 + r) * D4 + j];   // broadcast
                ffma2(s[r][0], xv.x, yv0.x); ffma2(s[r][0], xv.y, yv0.y);
                ffma2(s[r][1], xv.x, yv1.x); ffma2(s[r][1], xv.y, yv1.y);
            }
        }

        bool v0 = (n0 + nl0) < n_end;
        bool v1 = (n0 + nl1) < n_end;
        float t0, t1;
        unpack2(ny0, t0, t1); float dn0 = t0 + t1;
        unpack2(ny1, t0, t1); float dn1 = t0 + t1;

        float lg0[4], lg1[4];
        #pragma unroll
        for (int r = 0; r < 4; r++) {
            float slo, shi, sv;
            unpack2(s[r][0], slo, shi); sv = slo + shi;
            lg0[r] = v0 ? fmaf(al[r], sv, -be[r] * dn0) : -INFINITY;
            unpack2(s[r][1], slo, shi); sv = slo + shi;
            lg1[r] = v1 ? fmaf(al[r], sv, -be[r] * dn1) : -INFINITY;
        }

        // ---- online softmax (4 rows) ----
        #pragma unroll
        for (int r = 0; r < 4; r++) {
            float mt = fmaxf(lg0[r], lg1[r]);
            #pragma unroll
            for (int off = 16; off > 0; off >>= 1)
                mt = fmaxf(mt, __shfl_xor_sync(0xffffffffu, mt, off));
            float mnew = fmaxf(mrun[r], mt);
            float sc = (mrun[r] == -INFINITY) ? 0.f : __expf(mrun[r] - mnew);
            float p0 = __expf(lg0[r] - mnew);
            float p1 = __expf(lg1[r] - mnew);
            float ps = p0 + p1;
            #pragma unroll
            for (int off = 16; off > 0; off >>= 1)
                ps += __shfl_xor_sync(0xffffffffu, ps, off);
            lrun[r] = lrun[r] * sc + ps;
            mrun[r] = mnew;
            u64 scp = pack2(sc, sc);
            #pragma unroll
            for (int i = 0; i < 8; i++) fmul2(acc[r][i], scp);
            sp[(warp * 4 + r) * BN + nl0] = pack2(p0, p0);
            sp[(warp * 4 + r) * BN + nl1] = pack2(p1, p1);
        }
        __syncwarp();

        // ---- PV ----
        #pragma unroll 2
        for (int n = 0; n < BN; n++) {
            u64 p0 = sp[(warp * 4 + 0) * BN + n];
            u64 p1 = sp[(warp * 4 + 1) * BN + n];
            u64 p2 = sp[(warp * 4 + 2) * BN + n];
            u64 p3 = sp[(warp * 4 + 3) * BN + n];
            #pragma unroll
            for (int k = 0; k < 4; k++) {
                int j = lane + 32 * k;
                ulonglong2 yv = sy[j * BN + (n ^ (j & 63))];
                ffma2(acc[0][2*k], p0, yv.x); ffma2(acc[0][2*k+1], p0, yv.y);
                ffma2(acc[1][2*k], p1, yv.x); ffma2(acc[1][2*k+1], p1, yv.y);
                ffma2(acc[2][2*k], p2, yv.x); ffma2(acc[2][2*k+1], p2, yv.y);
                ffma2(acc[3][2*k], p3, yv.x); ffma2(acc[3][2*k+1], p3, yv.y);
            }
        }
    }

    // ---- write per-(row,split) partials ----
    {
        ulonglong2* gacc2 = (ulonglong2*)g_acc;
        #pragma unroll
        for (int r = 0; r < 4; r++) {
            int row = r0 + warp * 4 + r;
            size_t base = ((size_t)row * NSPLIT + split) * D4;
            #pragma unroll
            for (int k = 0; k < 4; k++)
                gacc2[base + lane + 32 * k] =
                    make_ulonglong2(acc[r][2*k], acc[r][2*k+1]);
            if (lane == 0) {
                g_ml[(row * NSPLIT + split) * 2 + 0] = mrun[r];
                g_ml[(row * NSPLIT + split) * 2 + 1] = lrun[r];
            }
        }
    }

    // ---- last-CTA combine epilogue ----
    __threadfence();
    __syncthreads();
    if (tid == 0) {
        int old = atomicAdd(&g_cnt[rb], 1);
        s_last = (old == NSPLIT - 1) ? 1 : 0;
    }
    __syncthreads();
    if (!s_last) return;
    __threadfence();

    {
        int row = r0 + (tid >> 3);           // 8 threads per row
        int jc  = tid & 7;
        float ms[NSPLIT], ls[NSPLIT];
        float M = -INFINITY;
        #pragma unroll
        for (int s = 0; s < NSPLIT; s++) {
            float2 ml = __ldcg((const float2*)&g_ml[(row * NSPLIT + s) * 2]);
            ms[s] = ml.x; ls[s] = ml.y;
            M = fmaxf(M, ms[s]);
        }
        float w[NSPLIT], L = 0.f;
        #pragma unroll
        for (int s = 0; s < NSPLIT; s++) {
            w[s] = __expf(ms[s] - M);
            L = fmaf(w[s], ls[s], L);
        }
        float a = t[row], b = 1.f - a;
        float c1 = -1.f / b;
        float c2 = (1.f + a / b) / L;

        const float4* gacc4 = (const float4*)g_acc;
        #pragma unroll 4
        for (int q = 0; q < 16; q++) {
            int j = jc + 8 * q;
            float4 ws = make_float4(0.f, 0.f, 0.f, 0.f);
            #pragma unroll
            for (int s = 0; s < NSPLIT; s++) {
                float4 v = __ldcg(&gacc4[((size_t)row * NSPLIT + s) * D4 + j]);
                ws.x = fmaf(w[s], v.x, ws.x); ws.y = fmaf(w[s], v.y, ws.y);
                ws.z = fmaf(w[s], v.z, ws.z); ws.w = fmaf(w[s], v.w, ws.w);
            }
            float4 xv = x4[(size_t)row * D4 + j];
            float4 o;
            o.x = fmaf(c1, xv.x, c2 * ws.x);
            o.y = fmaf(c1, xv.y, c2 * ws.y);
            o.z = fmaf(c1, xv.z, c2 * ws.z);
            o.w = fmaf(c1, xv.w, c2 * ws.w);
            ((float4*)out)[(size_t)row * D4 + j] = o;
        }
    }
    __syncthreads();
    if (tid == 0) g_cnt[rb] = 0;   // reset for next graph replay
}

// ---------------------------------------------------------------------------
extern "C" void kernel_launch(void* const* d_in, const int* in_sizes, int n_in,
                              void* d_out, int out_size)
{
    const float* x = (const float*)d_in[0];   // x_t (1024,512)
    const float* t = (const float*)d_in[1];   // t (1024,)
    const float* y = (const float*)d_in[2];   // dataset (100000,512)
    float* out = (float*)d_out;

    cudaFuncSetAttribute(flash_kernel,
                         cudaFuncAttributeMaxDynamicSharedMemorySize, SMEM_BYTES);
    flash_kernel<<<dim3(NROWBLK, NSPLIT), THREADS, SMEM_BYTES>>>(x, t, y, out);
}